// round 13
// baseline (speedup 1.0000x reference)
#include <cuda_runtime.h>

// CutStripes: out[b,0,t,f] = mask(b,t) ? x[perm[b],0,t,f] : x[b,0,t,f]
// B=128, C=1, T=2048, F=128 (fp32). HBM-bound row-select copy.
// R13 (= R10..R12 re-bench; broker timeouts, no data):
//   sm_103a requires .v8.b32 (256-bit) for L2::evict_last ld; .L2::no_allocate
//   st is illegal -> use st.global.cs. x loads = LDG.256 evict_last (pin x in L2),
//   out stores = evict-first streaming. ILP=4 rows/thread, 32B lane each.

#define B_ 128
#define T_ 2048
#define F_ 128
#define STRIPES 4
#define ILP 4
#define LANES 16   // 16 x 32B = 512B = one F-row

struct V8 { float4 a, b; };

__device__ __forceinline__ V8 ldg256_evict_last(const float* p) {
    unsigned r0,r1,r2,r3,r4,r5,r6,r7;
    asm volatile("ld.global.nc.L2::evict_last.v8.b32 {%0,%1,%2,%3,%4,%5,%6,%7}, [%8];"
                 : "=r"(r0),"=r"(r1),"=r"(r2),"=r"(r3),
                   "=r"(r4),"=r"(r5),"=r"(r6),"=r"(r7)
                 : "l"(p));
    V8 v;
    v.a.x=__uint_as_float(r0); v.a.y=__uint_as_float(r1);
    v.a.z=__uint_as_float(r2); v.a.w=__uint_as_float(r3);
    v.b.x=__uint_as_float(r4); v.b.y=__uint_as_float(r5);
    v.b.z=__uint_as_float(r6); v.b.w=__uint_as_float(r7);
    return v;
}

__global__ void __launch_bounds__(256)
cutstripes_kernel(const float* __restrict__ x,
                  const int*   __restrict__ perm,
                  const int*   __restrict__ bgn,
                  const int*   __restrict__ dist,
                  float*       __restrict__ out)
{
    int i       = blockIdx.x * blockDim.x + threadIdx.x;  // [0, B_*T_*LANES/ILP)
    int lane    = i & (LANES - 1);                        // 32B chunk within row
    int rowBase = (i >> 4) * ILP;                         // b*T + t0
    int t0      = rowBase & (T_ - 1);                     // ILP | 2048 -> same b
    int b       = rowBase >> 11;

    // Stripe params for this b (warp-uniform broadcast loads).
    int lo0 = __ldg(&bgn[b * STRIPES + 0]), d0 = __ldg(&dist[b * STRIPES + 0]);
    int lo1 = __ldg(&bgn[b * STRIPES + 1]), d1 = __ldg(&dist[b * STRIPES + 1]);
    int lo2 = __ldg(&bgn[b * STRIPES + 2]), d2 = __ldg(&dist[b * STRIPES + 2]);
    int lo3 = __ldg(&bgn[b * STRIPES + 3]), d3 = __ldg(&dist[b * STRIPES + 3]);
    int p   = __ldg(&perm[b]);

    V8 v[ILP];
#pragma unroll
    for (int k = 0; k < ILP; k++) {
        int t = t0 + k;
        bool m = (t >= lo0 && t < lo0 + d0) |
                 (t >= lo1 && t < lo1 + d1) |
                 (t >= lo2 && t < lo2 + d2) |
                 (t >= lo3 && t < lo3 + d3);
        int src = m ? p : b;
        // element offset: (src*T + t)*128 + lane*8
        v[k] = ldg256_evict_last(&x[(((src << 11) | t) << 7) + (lane << 3)]);
    }

#pragma unroll
    for (int k = 0; k < ILP; k++) {
        float4* o = (float4*)&out[(((rowBase + k) << 7)) + (lane << 3)];
        __stcs(o,     v[k].a);     // evict-first streaming stores
        __stcs(o + 1, v[k].b);
    }
}

extern "C" void kernel_launch(void* const* d_in, const int* in_sizes, int n_in,
                              void* d_out, int out_size)
{
    const float* x    = (const float*)d_in[0];
    const int*   perm = (const int*)d_in[1];
    const int*   bgn  = (const int*)d_in[2];
    const int*   dist = (const int*)d_in[3];
    float*       out  = (float*)d_out;

    const int total   = B_ * T_ * LANES / ILP;   // 1,048,576 threads
    const int threads = 256;
    const int blocks  = total / threads;         // 4096

    cutstripes_kernel<<<blocks, threads>>>(x, perm, bgn, dist, out);
}

// round 16
// speedup vs baseline: 1.0537x; 1.0537x over previous
#include <cuda_runtime.h>

// CutStripes: out[b,0,t,f] = mask(b,t) ? x[perm[b],0,t,f] : x[b,0,t,f]
// B=128, C=1, T=2048, F=128 (fp32). HBM-bound row-select copy.
// R16 (= R14/R15 re-bench; broker timeouts, no data):
//      R2 structure (float4 loads, ILP=4, 36.8us baseline); single delta =
//      stores __stcs -> __stwt (write-through, no L2 line allocation; closest
//      legal analog of st.L2::no_allocate which ptxas rejects).
//      evict_last + LDG.256 (R13) regressed and are abandoned.

#define B_ 128
#define T_ 2048
#define F_ 128
#define STRIPES 4
#define ILP 4

__global__ void __launch_bounds__(256)
cutstripes_kernel(const float4* __restrict__ x4,
                  const int*    __restrict__ perm,
                  const int*    __restrict__ bgn,
                  const int*    __restrict__ dist,
                  float4*       __restrict__ out4)
{
    int i       = blockIdx.x * blockDim.x + threadIdx.x;  // [0, B_*T_*32/ILP)
    int lane    = i & 31;                                 // float4 index within row
    int rowBase = (i >> 5) * ILP;                         // b*T + t0
    int t0      = rowBase & (T_ - 1);                     // ILP | 2048 -> same b
    int b       = rowBase >> 11;

    // Stripe params for this b (warp-uniform broadcast loads).
    int lo0 = __ldg(&bgn[b * STRIPES + 0]), d0 = __ldg(&dist[b * STRIPES + 0]);
    int lo1 = __ldg(&bgn[b * STRIPES + 1]), d1 = __ldg(&dist[b * STRIPES + 1]);
    int lo2 = __ldg(&bgn[b * STRIPES + 2]), d2 = __ldg(&dist[b * STRIPES + 2]);
    int lo3 = __ldg(&bgn[b * STRIPES + 3]), d3 = __ldg(&dist[b * STRIPES + 3]);
    int p   = __ldg(&perm[b]);

    float4 v[ILP];
#pragma unroll
    for (int k = 0; k < ILP; k++) {
        int t = t0 + k;
        bool m = (t >= lo0 && t < lo0 + d0) |
                 (t >= lo1 && t < lo1 + d1) |
                 (t >= lo2 && t < lo2 + d2) |
                 (t >= lo3 && t < lo3 + d3);
        int src = m ? p : b;
        v[k] = __ldg(&x4[(((src << 11) | t) << 5) + lane]);  // (src*T+t)*32+lane
    }

#pragma unroll
    for (int k = 0; k < ILP; k++) {
        // Write-through: no L2 line allocation for the never-re-read output.
        __stwt(&out4[((rowBase + k) << 5) + lane], v[k]);
    }
}

extern "C" void kernel_launch(void* const* d_in, const int* in_sizes, int n_in,
                              void* d_out, int out_size)
{
    const float4* x4   = (const float4*)d_in[0];
    const int*    perm = (const int*)d_in[1];
    const int*    bgn  = (const int*)d_in[2];
    const int*    dist = (const int*)d_in[3];
    float4*       out4 = (float4*)d_out;

    const int total   = B_ * T_ * (F_ / 4) / ILP;  // 2,097,152 threads
    const int threads = 256;
    const int blocks  = total / threads;           // 8192

    cutstripes_kernel<<<blocks, threads>>>(x4, perm, bgn, dist, out4);
}